// round 17
// baseline (speedup 1.0000x reference)
#include <cuda_runtime.h>
#include <cuda_bf16.h>
#include <cstdint>

typedef unsigned long long u64;

// Problem constants
constexpr int Bb  = 2;
constexpr int NC  = 256;
constexpr int CN  = 256;
constexpr int K   = 16;
constexpr int DN  = 64;
constexpr int HM  = 128;
constexpr int F   = 192;
constexpr int HMOD = 64;
constexpr int MOD_OUT = 5;

// Scratch
__device__ float g_pooled[(size_t)Bb * NC * 2 * DN];    // raw sums; /CN in mod
// Pre-converted bf16 hi/lo smem-image tiles (final swizzled layout)
__device__ uint8_t g_wimg[16 * 131072];                 // [mlp*8+g]: 3x32KB W1 + 32KB W2 (hi16+lo16 each)
__device__ uint8_t g_himg[(size_t)Bb * NC * 65536];     // h   B-tiles [256x64] (hi32 + lo32)
__device__ uint8_t g_nimg[(size_t)NC * 65536];          // nid B-tiles
__device__ uint8_t g_aimg[(size_t)Bb * NC * 65536];     // agg B-tiles

// ---------------- SMEM layout (bytes), bf16 operands, c-half CTA -----------
constexpr int OFF_TMEM  = 0;
constexpr int OFF_MBARA = 8;
constexpr int OFF_MBARB = 16;
constexpr int OFF_MBARC = 24;
constexpr int OFF_B1M   = 32;     // 128 f
constexpr int OFF_B2M   = 544;    // 64 f
constexpr int OFF_B1SS  = 800;    // 128 f
constexpr int OFF_B2SS  = 1312;   // 64 f
constexpr int OFF_AH    = 2048;             // 16KB  (W1 chunk / W2)
constexpr int OFF_AL    = 2048 + 16384;     // 16KB
constexpr int OFF_BH    = 2048 + 32768;     // 16KB  (feat c-half / hidden k-half)
constexpr int OFF_BL    = 2048 + 49152;     // 16KB
constexpr int SMEM_MLP  = 2048 + 65536;     // 67584 B -> 3 CTAs/SM

constexpr int SMEM_AGG  = 65536 + 16384 + 16384;   // 98304 B

#if defined(__CUDA_ARCH_FEAT_SM103_ALL) || defined(__CUDA_ARCH_FEAT_SM100_ALL) || defined(__CUDA_ARCH_FEAT_SM101_ALL)
#define HAS_TCGEN05 1
#else
#define HAS_TCGEN05 0
#endif

__device__ __forceinline__ uint32_t smem_u32(const void* p) {
    uint32_t a;
    asm("{ .reg .u64 t; cvta.to.shared.u64 t, %1; cvt.u32.u64 %0, t; }"
        : "=r"(a) : "l"(p));
    return a;
}

#if HAS_TCGEN05
__device__ __forceinline__ uint32_t elect1() {
    uint32_t p;
    asm volatile("{ .reg .pred p; elect.sync _|p, 0xFFFFFFFF; selp.b32 %0, 1, 0, p; }"
                 : "=r"(p));
    return p;
}

#define TC_ALLOC(smem_addr, n) \
    asm volatile("tcgen05.alloc.cta_group::1.sync.aligned.shared::cta.b32 [%0], %1;" \
                 :: "r"((uint32_t)(smem_addr)), "r"((uint32_t)(n)) : "memory")
#define TC_RELINQ() \
    asm volatile("tcgen05.relinquish_alloc_permit.cta_group::1.sync.aligned;")
#define TC_DEALLOC(tmem, n) \
    asm volatile("tcgen05.dealloc.cta_group::1.sync.aligned.b32 %0, %1;" \
                 :: "r"(tmem), "r"((uint32_t)(n)))
#define TC_COMMIT(mbar) \
    asm volatile("tcgen05.commit.cta_group::1.mbarrier::arrive::one.shared::cluster.b64 [%0];" \
                 :: "r"((uint32_t)(mbar)) : "memory")
#define TC_FENCE_AFTER()  asm volatile("tcgen05.fence::after_thread_sync;" ::: "memory")
#define TC_WAIT_LD()      asm volatile("tcgen05.wait::ld.sync.aligned;" ::: "memory")

#define LDTM_X32(r, addr) \
    asm volatile( \
        "tcgen05.ld.sync.aligned.32x32b.x32.b32 " \
        "{%0, %1, %2, %3, %4, %5, %6, %7, " \
        " %8, %9, %10, %11, %12, %13, %14, %15, " \
        " %16, %17, %18, %19, %20, %21, %22, %23, " \
        " %24, %25, %26, %27, %28, %29, %30, %31}, [%32];" \
        : "=r"((r)[0]),  "=r"((r)[1]),  "=r"((r)[2]),  "=r"((r)[3]), \
          "=r"((r)[4]),  "=r"((r)[5]),  "=r"((r)[6]),  "=r"((r)[7]), \
          "=r"((r)[8]),  "=r"((r)[9]),  "=r"((r)[10]), "=r"((r)[11]), \
          "=r"((r)[12]), "=r"((r)[13]), "=r"((r)[14]), "=r"((r)[15]), \
          "=r"((r)[16]), "=r"((r)[17]), "=r"((r)[18]), "=r"((r)[19]), \
          "=r"((r)[20]), "=r"((r)[21]), "=r"((r)[22]), "=r"((r)[23]), \
          "=r"((r)[24]), "=r"((r)[25]), "=r"((r)[26]), "=r"((r)[27]), \
          "=r"((r)[28]), "=r"((r)[29]), "=r"((r)[30]), "=r"((r)[31]) \
        : "r"(addr))

__device__ __forceinline__ void mma_bf16_ss(uint32_t d_tmem, u64 a_desc, u64 b_desc,
                                            uint32_t idesc, uint32_t enable) {
    asm volatile(
        "{\n\t"
        ".reg .pred p;\n\t"
        "setp.ne.u32 p, %4, 0;\n\t"
        "tcgen05.mma.cta_group::1.kind::f16 [%0], %1, %2, %3, {%5, %5, %5, %5}, p;\n\t"
        "}"
        :: "r"(d_tmem), "l"(a_desc), "l"(b_desc), "r"(idesc), "r"(enable), "r"(0u)
        : "memory");
}
#endif  // HAS_TCGEN05

#define MBAR_INIT(mbar, cnt) \
    asm volatile("mbarrier.init.shared.b64 [%0], %1;" \
                 :: "r"((uint32_t)(mbar)), "r"((uint32_t)(cnt)) : "memory")

#define MBAR_WAIT(mbar, parity) do {                                           \
    uint32_t _m = (uint32_t)(mbar), _p = (uint32_t)(parity), _d;               \
    asm volatile("{ .reg .pred p;"                                             \
        " mbarrier.try_wait.parity.acquire.cta.shared::cta.b64 p, [%1], %2;"   \
        " selp.b32 %0, 1, 0, p; }" : "=r"(_d) : "r"(_m), "r"(_p) : "memory");  \
    while (!_d) {                                                              \
        asm volatile("{ .reg .pred p;"                                         \
            " mbarrier.try_wait.parity.acquire.cta.shared::cta.b64 p, [%1], %2, 0x989680;" \
            " selp.b32 %0, 1, 0, p; }" : "=r"(_d) : "r"(_m), "r"(_p) : "memory"); \
    }                                                                          \
} while (0)

constexpr u64 DESC_BASE = (2ull << 61) | (1ull << 46) | (64ull << 32) | (1ull << 16);
__device__ __forceinline__ u64 mk_desc(uint32_t addr) {
    return DESC_BASE | ((u64)(addr >> 4) & 0x3FFF);
}

// Blocked-atom + SW128 byte offset for bf16 tiles. atom = 8 rows x 64 bf16 (128B).
__device__ __forceinline__ uint32_t tile_off2(int row, int k, int atom_rows) {
    uint32_t o = ((uint32_t)((k >> 6) * atom_rows + (row >> 3)) << 10)
               + ((uint32_t)(row & 7) << 7) + ((uint32_t)(k & 63) << 1);
    return o ^ ((o >> 3) & 0x70);
}

// Inverse map: 4B image word index -> (row, k). Swizzle is an involution.
__device__ __forceinline__ void inv_tile(uint32_t word_idx, int R, int& row, int& k) {
    uint32_t dsw = word_idx * 4;
    uint32_t raw = dsw ^ ((dsw >> 3) & 0x70);
    uint32_t atom = raw >> 10;
    row = (int)((atom % R) * 8 + ((raw >> 7) & 7));
    k   = (int)((atom / R) * 64 + ((raw & 127) >> 1));
}

__device__ __forceinline__ void conv_pair(float x, float y, uint32_t& hi, uint32_t& lo) {
    __nv_bfloat162 h2 = __floats2bfloat162_rn(x, y);
    float lx = x - __bfloat162float(__low2bfloat16(h2));
    float ly = y - __bfloat162float(__high2bfloat16(h2));
    __nv_bfloat162 l2 = __floats2bfloat162_rn(lx, ly);
    hi = *reinterpret_cast<uint32_t*>(&h2);
    lo = *reinterpret_cast<uint32_t*>(&l2);
}

__device__ __forceinline__ float gelu_f(float x) {
    float x3 = x * x * x;
    return 0.5f * x * (1.0f + tanhf(0.7978845608028654f * (x + 0.044715f * x3)));
}

__device__ __forceinline__ float gelu_fast(float x) {
    float z = x + 0.044715f * x * x * x;
    float a = 2.3022081852f * z;
    float e;
    asm("ex2.approx.f32 %0, %1;" : "=f"(e) : "f"(a));
    float r;
    asm("rcp.approx.f32 %0, %1;" : "=f"(r) : "f"(e + 1.0f));
    return x - x * r;
}

constexpr uint32_t ID_BF = (1u << 4) | (1u << 7) | (1u << 10) | (8u << 17) | (8u << 24);

// ---------------------------------------------------------------------------
// Kernel 1: aggregation -> agg + h B-tile images; zeroes g_pooled[bn].
// ---------------------------------------------------------------------------
__global__ __launch_bounds__(512) void agg_kernel(
    const float* __restrict__ h,
    const float* __restrict__ w_conn,
    const int*   __restrict__ conn)
{
    extern __shared__ float smf[];
    int*   ci_sm = (int*)(smf + CN * DN);
    float* wc_sm = (float*)(ci_sm + CN * K);

    int bn   = blockIdx.x;
    int n    = bn & (NC - 1);
    int tid  = threadIdx.x;
    int wid  = tid >> 5;
    int lane = tid & 31;

    if (tid < 2 * DN) g_pooled[(size_t)bn * 2 * DN + tid] = 0.0f;

    const float4* hg = reinterpret_cast<const float4*>(h) + (size_t)bn * CN * DN / 4;
    float4* h_sm4 = reinterpret_cast<float4*>(smf);
    #pragma unroll
    for (int p = 0; p < 8; p++) h_sm4[p * 512 + tid] = hg[p * 512 + tid];

    const int4*   cg4 = reinterpret_cast<const int4*>(conn   + (size_t)n  * CN * K);
    const float4* wg4 = reinterpret_cast<const float4*>(w_conn + (size_t)bn * CN * K);
    int4*   ci4 = reinterpret_cast<int4*>(ci_sm);
    float4* wc4 = reinterpret_cast<float4*>(wc_sm);
    #pragma unroll
    for (int p = 0; p < 2; p++) {
        ci4[p * 512 + tid] = cg4[p * 512 + tid];
        wc4[p * 512 + tid] = wg4[p * 512 + tid];
    }
    __syncthreads();

    // emit h image from the smem tile -> swizzled bf16 hi/lo
    {
        uint32_t* dh = (uint32_t*)(g_himg + (size_t)bn * 65536);
        uint32_t* dl = dh + 8192;
        #pragma unroll
        for (int p = 0; p < 16; p++) {
            int i = p * 512 + tid;
            int row, k; inv_tile(i, 32, row, k);
            uint32_t hv, lv;
            conv_pair(smf[row * DN + k], smf[row * DN + k + 1], hv, lv);
            dh[i] = hv; dl[i] = lv;
        }
    }

    uint8_t* img = g_aimg + (size_t)bn * 65536;

    #pragma unroll
    for (int it = 0; it < 4; it++) {
        int c0 = wid * 16 + it * 4;
        const int*   ci0 = ci_sm + c0 * K;
        const float* wc0 = wc_sm + c0 * K;

        float2 a0 = {0,0}, a1 = {0,0}, a2 = {0,0}, a3 = {0,0};
        const float* hl = smf + lane * 2;
        #pragma unroll
        for (int k = 0; k < K; k++) {
            int i0 = ci0[k], i1 = ci0[K + k], i2 = ci0[2 * K + k], i3 = ci0[3 * K + k];
            float w0 = wc0[k], w1 = wc0[K + k], w2 = wc0[2 * K + k], w3 = wc0[3 * K + k];
            float2 v0 = *reinterpret_cast<const float2*>(hl + (size_t)i0 * DN);
            float2 v1 = *reinterpret_cast<const float2*>(hl + (size_t)i1 * DN);
            float2 v2 = *reinterpret_cast<const float2*>(hl + (size_t)i2 * DN);
            float2 v3 = *reinterpret_cast<const float2*>(hl + (size_t)i3 * DN);
            a0.x = fmaf(w0, v0.x, a0.x); a0.y = fmaf(w0, v0.y, a0.y);
            a1.x = fmaf(w1, v1.x, a1.x); a1.y = fmaf(w1, v1.y, a1.y);
            a2.x = fmaf(w2, v2.x, a2.x); a2.y = fmaf(w2, v2.y, a2.y);
            a3.x = fmaf(w3, v3.x, a3.x); a3.y = fmaf(w3, v3.y, a3.y);
        }
        #pragma unroll
        for (int cc = 0; cc < 4; cc++) {
            float2 a = (cc == 0) ? a0 : (cc == 1) ? a1 : (cc == 2) ? a2 : a3;
            uint32_t hv, lv; conv_pair(a.x, a.y, hv, lv);
            uint32_t off = tile_off2(c0 + cc, lane * 2, 32);
            *reinterpret_cast<uint32_t*>(img + off)         = hv;
            *reinterpret_cast<uint32_t*>(img + 32768 + off) = lv;
        }
    }
}

// ---------------------------------------------------------------------------
// Pre-conversion: weights. 16 blocks.
// ---------------------------------------------------------------------------
__global__ __launch_bounds__(512) void preconv_w(
    const float* __restrict__ mw1, const float* __restrict__ mw2,
    const float* __restrict__ sw1, const float* __restrict__ sw2)
{
    int b = blockIdx.x;
    int mlp = b >> 3, g = b & 7;
    const float* w1 = (mlp ? sw1 : mw1) + (size_t)g * HM * F;
    const float* w2 = (mlp ? sw2 : mw2) + (size_t)g * DN * HM;
    uint8_t* img = g_wimg + (size_t)b * 131072;
    int tid = threadIdx.x;

    #pragma unroll
    for (int t = 0; t < 3; t++) {
        uint32_t* dh = (uint32_t*)(img + t * 32768);
        uint32_t* dl = dh + 4096;
        for (int i = tid; i < 4096; i += 512) {
            int row, k; inv_tile(i, 16, row, k);
            uint32_t hv, lv;
            conv_pair(w1[(size_t)row * F + t * 64 + k],
                      w1[(size_t)row * F + t * 64 + k + 1], hv, lv);
            dh[i] = hv; dl[i] = lv;
        }
    }
    {
        uint32_t* dh = (uint32_t*)(img + 98304);
        uint32_t* dl = dh + 4096;
        for (int i = tid; i < 4096; i += 512) {
            int row, k; inv_tile(i, 8, row, k);
            uint32_t hv, lv;
            conv_pair(w2[(size_t)row * HM + k], w2[(size_t)row * HM + k + 1], hv, lv);
            dh[i] = hv; dl[i] = lv;
        }
    }
}

// ---------------------------------------------------------------------------
// Pre-conversion: neuron_id B-tiles. 256 blocks.
// ---------------------------------------------------------------------------
__global__ __launch_bounds__(512) void preconv_n(const float* __restrict__ nid)
{
    int nn = blockIdx.x;
    const float* src = nid + (size_t)nn * CN * DN;
    uint32_t* dh = (uint32_t*)(g_nimg + (size_t)nn * 65536);
    uint32_t* dl = dh + 8192;
    int tid = threadIdx.x;
    #pragma unroll
    for (int p = 0; p < 16; p++) {
        int i = p * 512 + tid;
        int row, k; inv_tile(i, 32, row, k);
        uint32_t hv, lv;
        conv_pair(src[(size_t)row * DN + k], src[(size_t)row * DN + k + 1], hv, lv);
        dh[i] = hv; dl[i] = lv;
    }
}

#if HAS_TCGEN05
// Copy a 16KB hi + 16KB lo tile into smem (pure uint4 memcpy).
__device__ __forceinline__ void copy_tile(char* smem, int off_h, int off_l,
                                          const uint8_t* sh, const uint8_t* sl, int tid) {
    const uint4* a = (const uint4*)sh;
    const uint4* b = (const uint4*)sl;
    uint4* dh = (uint4*)(smem + off_h);
    uint4* dl = (uint4*)(smem + off_l);
    #pragma unroll
    for (int p = 0; p < 8; p++) {
        int i = p * 128 + tid;
        dh[i] = a[i];
        dl[i] = b[i];
    }
}

// GEMM1 MMA for one K=64 tile: D1[j=128][c=128] over 2 N=64 chunks.
__device__ __forceinline__ void gemm1_mma(uint32_t sbase, uint32_t tmem, bool first) {
    u64 dah = mk_desc(sbase + OFF_AH), dal = mk_desc(sbase + OFF_AL);
    u64 dbh = mk_desc(sbase + OFF_BH), dbl = mk_desc(sbase + OFF_BL);
    if (elect1()) {
        #pragma unroll
        for (int pass = 0; pass < 3; pass++) {
            u64 da = (pass == 2) ? dal : dah;
            u64 db = (pass == 1) ? dbl : dbh;
            #pragma unroll
            for (int q = 0; q < 2; q++) {
                #pragma unroll
                for (int s = 0; s < 4; s++) {
                    mma_bf16_ss(tmem + q * 64, da + (u64)(s * 2),
                                db + (u64)(s * 2 + q * 512), ID_BF,
                                (first && pass == 0 && s == 0) ? 0u : 1u);
                }
            }
        }
        TC_COMMIT(sbase + OFF_MBARA);
    }
}

// GEMM2 k-half MMA: D2[c=128][j2=64] += hidden(B-buf) x W2(A-buf, k-half kh).
__device__ __forceinline__ void gemm2_mma(uint32_t sbase, uint32_t tmem, int kh,
                                          uint32_t mbar_off) {
    u64 dah = mk_desc(sbase + OFF_BH), dal = mk_desc(sbase + OFF_BL);   // A = hidden
    u64 dbh = mk_desc(sbase + OFF_AH), dbl = mk_desc(sbase + OFF_AL);   // B = W2
    if (elect1()) {
        #pragma unroll
        for (int pass = 0; pass < 3; pass++) {
            u64 da = (pass == 2) ? dal : dah;
            u64 db = (pass == 1) ? dbl : dbh;
            #pragma unroll
            for (int s = 0; s < 4; s++) {
                mma_bf16_ss(tmem, da + (u64)(s * 2),
                            db + (u64)(kh * 512 + s * 2), ID_BF,
                            (kh == 0 && pass == 0 && s == 0) ? 0u : 1u);
            }
        }
        TC_COMMIT(sbase + mbar_off);
    }
}

// GEMM2 phase: D1[j lanes][c cols 0..127] -> gelu hidden, two k-half MMAs.
// Warps 0,1 own j=k 0..63 (kh0 tile); warps 2,3 own j 64..127 (kh1 tile).
// Warps 2,3 pre-read D1 cols 0..63 before kh0's MMA overwrites them with D2.
__device__ __forceinline__ void gemm2_phase(
    char* smem, uint32_t sbase, uint32_t tmem,
    int wid, int lane, float bj1, uint32_t parity)
{
    int j = wid * 32 + lane;
    float fv[64];
    if (wid < 2) {
        #pragma unroll
        for (int cc = 0; cc < 4; cc++) {
            uint32_t r[32];
            LDTM_X32(r, tmem + cc * 32);
            TC_WAIT_LD();
            #pragma unroll
            for (int i2 = 0; i2 < 32; i2++) {
                float v = gelu_fast(__uint_as_float(r[i2]) + bj1);
                __nv_bfloat16 hb = __float2bfloat16(v);
                __nv_bfloat16 lb = __float2bfloat16(v - __bfloat162float(hb));
                uint32_t off = tile_off2(cc * 32 + i2, j, 16);
                *reinterpret_cast<__nv_bfloat16*>(smem + OFF_BH + off) = hb;
                *reinterpret_cast<__nv_bfloat16*>(smem + OFF_BL + off) = lb;
            }
        }
    } else {
        #pragma unroll
        for (int cc = 0; cc < 2; cc++) {
            uint32_t r[32];
            LDTM_X32(r, tmem + cc * 32);
            TC_WAIT_LD();
            #pragma unroll
            for (int i2 = 0; i2 < 32; i2++)
                fv[cc * 32 + i2] = gelu_fast(__uint_as_float(r[i2]) + bj1);
        }
    }
    asm volatile("fence.proxy.async.shared::cta;" ::: "memory");
    __syncthreads();

    if (wid == 0) gemm2_mma(sbase, tmem, 0, OFF_MBARB);
    MBAR_WAIT(sbase + OFF_MBARB, parity);
    TC_FENCE_AFTER();

    if (wid >= 2) {
        int kl = j - 64;
        #pragma unroll
        for (int i2 = 0; i2 < 64; i2++) {
            __nv_bfloat16 hb = __float2bfloat16(fv[i2]);
            __nv_bfloat16 lb = __float2bfloat16(fv[i2] - __bfloat162float(hb));
            uint32_t off = tile_off2(i2, kl, 16);
            *reinterpret_cast<__nv_bfloat16*>(smem + OFF_BH + off) = hb;
            *reinterpret_cast<__nv_bfloat16*>(smem + OFF_BL + off) = lb;
        }
        #pragma unroll
        for (int cc = 2; cc < 4; cc++) {
            uint32_t r[32];
            LDTM_X32(r, tmem + cc * 32);           // D1 cols 64..127 still intact
            TC_WAIT_LD();
            #pragma unroll
            for (int i2 = 0; i2 < 32; i2++) {
                float v = gelu_fast(__uint_as_float(r[i2]) + bj1);
                __nv_bfloat16 hb = __float2bfloat16(v);
                __nv_bfloat16 lb = __float2bfloat16(v - __bfloat162float(hb));
                uint32_t off = tile_off2(cc * 32 + i2, kl, 16);
                *reinterpret_cast<__nv_bfloat16*>(smem + OFF_BH + off) = hb;
                *reinterpret_cast<__nv_bfloat16*>(smem + OFF_BL + off) = lb;
            }
        }
    }
    asm volatile("fence.proxy.async.shared::cta;" ::: "memory");
    __syncthreads();

    if (wid == 0) gemm2_mma(sbase, tmem, 1, OFF_MBARC);
    MBAR_WAIT(sbase + OFF_MBARC, parity);
    TC_FENCE_AFTER();
}
#endif  // HAS_TCGEN05

// ---------------------------------------------------------------------------
// Fused per-(b,n,c-half) kernel: 128 threads, 3 CTAs/SM, TMEM 128 cols.
// ---------------------------------------------------------------------------
__global__ __launch_bounds__(128, 3)
void fused_mlp_kernel(
    const float* __restrict__ h,
    const float* __restrict__ ctx,
    const float* __restrict__ mb1, const float* __restrict__ mb2,
    const float* __restrict__ sw1,
    const float* __restrict__ sb1, const float* __restrict__ sb2,
    const int*   __restrict__ c2g,
    float*       __restrict__ o_msg,
    float*       __restrict__ o_h)
{
    extern __shared__ char smem[];
    uint32_t sbase = smem_u32(smem);

    int tid  = threadIdx.x;
    int wid  = tid >> 5;
    int lane = tid & 31;
    int bn   = blockIdx.x >> 1;
    int chh  = blockIdx.x & 1;        // c-half
    int n    = bn & (NC - 1);
    int g    = c2g[n];

    const float* base_h = h + (size_t)bn * CN * DN;
    const float* base_c = ctx + (size_t)bn * DN;
    const float* w1s    = sw1 + (size_t)g * HM * F;

#if HAS_TCGEN05
    const uint8_t* wim = g_wimg + (size_t)g * 131072;
    const uint8_t* wis = g_wimg + (size_t)(8 + g) * 131072;
    const uint8_t* him = g_himg + (size_t)bn * 65536;
    const uint8_t* aim = g_aimg + (size_t)bn * 65536;
    const uint8_t* nim = g_nimg + (size_t)n * 65536;
    const int choff = chh * 16384;    // c-half offset within B-tile image (hi part)

    if (wid == 0) {
        TC_ALLOC(sbase + OFF_TMEM, 128);
        TC_RELINQ();
    }
    if (tid == 0) {
        MBAR_INIT(sbase + OFF_MBARA, 1);
        MBAR_INIT(sbase + OFF_MBARB, 1);
        MBAR_INIT(sbase + OFF_MBARC, 1);
    }
    ((float*)(smem + OFF_B1M))[tid]  = mb1[g * HM + tid];
    ((float*)(smem + OFF_B1SS))[tid] = sb1[g * HM + tid];
    if (tid < DN) {
        ((float*)(smem + OFF_B2M))[tid]  = mb2[g * DN + tid];
        ((float*)(smem + OFF_B2SS))[tid] = sb2[g * DN + tid];
    }
    __syncthreads();

    // rank-1 ctx fold: B1SS[j] += dot(W1s[j][128:192], ctx)  (fp32, exact)
    {
        const float* wr = w1s + (size_t)tid * F + 128;
        float acc = 0.0f;
        #pragma unroll
        for (int f = 0; f < 64; f++) acc = fmaf(wr[f], base_c[f], acc);
        ((float*)(smem + OFF_B1SS))[tid] += acc;
    }

    uint32_t tmem;
    asm("ld.shared.b32 %0, [%1];" : "=r"(tmem) : "r"(sbase + OFF_TMEM));

    uint32_t ph = 0;
    int j = wid * 32 + lane;

    // ===================== MSG GEMM1 (3 K-tiles of 64) =====================
    for (int t = 0; t < 3; t++) {
        if (t > 0) { MBAR_WAIT(sbase + OFF_MBARA, ph); ph ^= 1; TC_FENCE_AFTER(); }
        copy_tile(smem, OFF_AH, OFF_AL, wim + t * 32768, wim + t * 32768 + 16384, tid);
        const uint8_t* bim = (t == 0) ? him : ((t == 1) ? aim : nim);
        copy_tile(smem, OFF_BH, OFF_BL, bim + choff, bim + 32768 + choff, tid);
        asm volatile("fence.proxy.async.shared::cta;" ::: "memory");
        __syncthreads();
        if (wid == 0) gemm1_mma(sbase, tmem, t == 0);
    }
    MBAR_WAIT(sbase + OFF_MBARA, ph); ph ^= 1;
    TC_FENCE_AFTER();

    // ===================== MSG GEMM2 =====================
    copy_tile(smem, OFF_AH, OFF_AL, wim + 98304, wim + 98304 + 16384, tid);
    float bj1m = ((float*)(smem + OFF_B1M))[j];
    gemm2_phase(smem, sbase, tmem, wid, lane, bj1m, 0);

    // ---- msg D2 epilogue: -> o_msg, pool, and state-t0 B tile ----
    {
        int c_loc = j;                       // D2 lanes = local c
        int c_glb = chh * 128 + c_loc;
        float mv[64];
        #pragma unroll
        for (int cc = 0; cc < 2; cc++) {
            uint32_t r[32];
            LDTM_X32(r, tmem + cc * 32);
            TC_WAIT_LD();
            #pragma unroll
            for (int i2 = 0; i2 < 32; i2++)
                mv[cc * 32 + i2] = __uint_as_float(r[i2])
                                 + ((float*)(smem + OFF_B2M))[cc * 32 + i2];
        }
        float* op = o_msg + ((size_t)bn * CN + c_glb) * DN;
        #pragma unroll
        for (int i4 = 0; i4 < 16; i4++)
            *reinterpret_cast<float4*>(op + i4 * 4) =
                make_float4(mv[i4 * 4], mv[i4 * 4 + 1], mv[i4 * 4 + 2], mv[i4 * 4 + 3]);
        #pragma unroll
        for (int i2 = 0; i2 < 64; i2++) {
            __nv_bfloat16 hb = __float2bfloat16(mv[i2]);
            __nv_bfloat16 lb = __float2bfloat16(mv[i2] - __bfloat162float(hb));
            uint32_t off = tile_off2(c_loc, i2, 16);
            *reinterpret_cast<__nv_bfloat16*>(smem + OFF_BH + off) = hb;
            *reinterpret_cast<__nv_bfloat16*>(smem + OFF_BL + off) = lb;
        }
        #pragma unroll
        for (int grp = 0; grp < 2; grp++) {
            float psum = 0.0f;
            #pragma unroll
            for (int i2 = 0; i2 < 32; i2++) {
                float v = mv[grp * 32 + i2];
                v += __shfl_xor_sync(0xFFFFFFFFu, v, 16);
                v += __shfl_xor_sync(0xFFFFFFFFu, v, 8);
                v += __shfl_xor_sync(0xFFFFFFFFu, v, 4);
                v += __shfl_xor_sync(0xFFFFFFFFu, v, 2);
                v += __shfl_xor_sync(0xFFFFFFFFu, v, 1);
                if (lane == i2) psum = v;
            }
            atomicAdd(&g_pooled[(size_t)bn * 2 * DN + DN + grp * 32 + lane], psum);
        }
    }
    asm volatile("fence.proxy.async.shared::cta;" ::: "memory");
    __syncthreads();

    // ===================== STATE GEMM1 (2 K-tiles: msg, h) =====================
    // t0: B = msg tile (just staged), A = W1s chunk 1 (cols 64:128)
    copy_tile(smem, OFF_AH, OFF_AL, wis + 32768, wis + 32768 + 16384, tid);
    asm volatile("fence.proxy.async.shared::cta;" ::: "memory");
    __syncthreads();
    if (wid == 0) gemm1_mma(sbase, tmem, true);

    MBAR_WAIT(sbase + OFF_MBARA, ph); ph ^= 1; TC_FENCE_AFTER();
    copy_tile(smem, OFF_AH, OFF_AL, wis, wis + 16384, tid);
    copy_tile(smem, OFF_BH, OFF_BL, him + choff, him + 32768 + choff, tid);
    asm volatile("fence.proxy.async.shared::cta;" ::: "memory");
    __syncthreads();
    if (wid == 0) gemm1_mma(sbase, tmem, false);
    MBAR_WAIT(sbase + OFF_MBARA, ph); ph ^= 1;
    TC_FENCE_AFTER();

    // ===================== STATE GEMM2 =====================
    copy_tile(smem, OFF_AH, OFF_AL, wis + 98304, wis + 98304 + 16384, tid);
    float bj1s = ((float*)(smem + OFF_B1SS))[j];
    gemm2_phase(smem, sbase, tmem, wid, lane, bj1s, 1);

    // ---- state D2 epilogue: + b2s + h residual -> o_h, pool ----
    {
        int c_loc = j;
        int c_glb = chh * 128 + c_loc;
        const float* hp = base_h + (size_t)c_glb * DN;
        float hv[64];
        #pragma unroll
        for (int cc = 0; cc < 2; cc++) {
            uint32_t r[32];
            LDTM_X32(r, tmem + cc * 32);
            TC_WAIT_LD();
            #pragma unroll
            for (int i2 = 0; i2 < 32; i2++)
                hv[cc * 32 + i2] = __uint_as_float(r[i2])
                                 + ((float*)(smem + OFF_B2SS))[cc * 32 + i2];
        }
        float* op = o_h + ((size_t)bn * CN + c_glb) * DN;
        #pragma unroll
        for (int i4 = 0; i4 < 16; i4++) {
            float4 hr = *reinterpret_cast<const float4*>(hp + i4 * 4);
            float4 v;
            v.x = hv[i4 * 4 + 0] + hr.x;
            v.y = hv[i4 * 4 + 1] + hr.y;
            v.z = hv[i4 * 4 + 2] + hr.z;
            v.w = hv[i4 * 4 + 3] + hr.w;
            hv[i4 * 4 + 0] = v.x; hv[i4 * 4 + 1] = v.y;
            hv[i4 * 4 + 2] = v.z; hv[i4 * 4 + 3] = v.w;
            *reinterpret_cast<float4*>(op + i4 * 4) = v;
        }
        #pragma unroll
        for (int grp = 0; grp < 2; grp++) {
            float psum = 0.0f;
            #pragma unroll
            for (int i2 = 0; i2 < 32; i2++) {
                float v = hv[grp * 32 + i2];
                v += __shfl_xor_sync(0xFFFFFFFFu, v, 16);
                v += __shfl_xor_sync(0xFFFFFFFFu, v, 8);
                v += __shfl_xor_sync(0xFFFFFFFFu, v, 4);
                v += __shfl_xor_sync(0xFFFFFFFFu, v, 2);
                v += __shfl_xor_sync(0xFFFFFFFFu, v, 1);
                if (lane == i2) psum = v;
            }
            atomicAdd(&g_pooled[(size_t)bn * 2 * DN + grp * 32 + lane], psum);
        }
    }

    __syncthreads();
    if (wid == 0) TC_DEALLOC(tmem, 128);

#else  // ---------------- SIMT fallback (plain compute_103 pass only) -------
    // Never executed on sm_103a (exact-arch cubin always selected).
    int c_glb = (blockIdx.x & 1) * 128 + tid;
    for (int f = 0; f < DN; f++) {
        o_msg[((size_t)bn * CN + c_glb) * DN + f] = 0.0f;
        o_h[((size_t)bn * CN + c_glb) * DN + f]   = base_h[(size_t)c_glb * DN + f];
    }
    (void)mb1; (void)mb2; (void)sb1; (void)sb2; (void)w1s; (void)base_c; (void)wid; (void)lane;
#endif
}

// ---------------------------------------------------------------------------
// Slim modulation MLP: reads pooled sums (raw), applies 1/CN.
// ---------------------------------------------------------------------------
__global__ __launch_bounds__(128) void mod_kernel(
    const float* __restrict__ mw1,
    const float* __restrict__ mb1,
    const float* __restrict__ mw2,
    const float* __restrict__ mb2,
    float*       __restrict__ mod)
{
    __shared__ float pooled[2 * DN];
    __shared__ float phh[HMOD];

    int bn  = blockIdx.x;
    int n   = bn & (NC - 1);
    int tid = threadIdx.x;

    if (tid < 2 * DN) pooled[tid] = g_pooled[(size_t)bn * 2 * DN + tid] * (1.0f / CN);
    __syncthreads();

    if (tid < HMOD) {
        const float* w = mw1 + (size_t)n * (2 * DN) * HMOD + tid;
        float acc = mb1[n * HMOD + tid];
        #pragma unroll 8
        for (int f = 0; f < 2 * DN; f++) acc = fmaf(pooled[f], w[f * HMOD], acc);
        phh[tid] = gelu_f(acc);
    }
    __syncthreads();

    if (tid < MOD_OUT) {
        const float* w = mw2 + (size_t)n * HMOD * MOD_OUT + tid;
        float acc = mb2[n * MOD_OUT + tid];
        #pragma unroll 8
        for (int k = 0; k < HMOD; k++) acc = fmaf(phh[k], w[k * MOD_OUT], acc);
        mod[bn * MOD_OUT + tid] = acc;
    }
}

// ---------------------------------------------------------------------------
// Launch (fused is launch #4 -> ncu capture target)
// ---------------------------------------------------------------------------
extern "C" void kernel_launch(void* const* d_in, const int* in_sizes, int n_in,
                              void* d_out, int out_size)
{
    const float* h      = (const float*)d_in[0];
    const float* w_conn = (const float*)d_in[1];
    const float* ctx    = (const float*)d_in[2];
    const float* nid    = (const float*)d_in[3];
    const float* mw1    = (const float*)d_in[4];
    const float* mb1    = (const float*)d_in[5];
    const float* mw2    = (const float*)d_in[6];
    const float* mb2    = (const float*)d_in[7];
    const float* sw1    = (const float*)d_in[8];
    const float* sb1    = (const float*)d_in[9];
    const float* sw2    = (const float*)d_in[10];
    const float* sb2    = (const float*)d_in[11];
    const float* modw1  = (const float*)d_in[12];
    const float* modb1  = (const float*)d_in[13];
    const float* modw2  = (const float*)d_in[14];
    const float* modb2  = (const float*)d_in[15];
    const int*   conn   = (const int*)d_in[16];
    const int*   c2g    = (const int*)d_in[17];

    float* out   = (float*)d_out;
    float* o_h   = out;
    float* o_msg = out + (size_t)Bb * NC * CN * DN;
    float* o_mod = o_msg + (size_t)Bb * NC * CN * DN;

    const int grid = Bb * NC;  // 512

    static bool attr_done = false;
    if (!attr_done) {
        cudaFuncSetAttribute(agg_kernel, cudaFuncAttributeMaxDynamicSharedMemorySize, SMEM_AGG);
        cudaFuncSetAttribute(fused_mlp_kernel, cudaFuncAttributeMaxDynamicSharedMemorySize, SMEM_MLP);
        attr_done = true;
    }

    agg_kernel<<<grid, 512, SMEM_AGG>>>(h, w_conn, conn);                 // #1
    preconv_w<<<16, 512>>>(mw1, mw2, sw1, sw2);                           // #2
    preconv_n<<<NC, 512>>>(nid);                                          // #3
    fused_mlp_kernel<<<grid * 2, 128, SMEM_MLP>>>(h, ctx, mb1, mb2,       // #4
                                                  sw1, sb1, sb2, c2g, o_msg, o_h);
    mod_kernel<<<grid, 128>>>(modw1, modb1, modw2, modb2, o_mod);         // #5
}